// round 6
// baseline (speedup 1.0000x reference)
#include <cuda_runtime.h>
#include <math.h>

#define N_B      32

__device__ __forceinline__ float2 cmul(float2 a, float2 b) {
    return make_float2(a.x * b.x - a.y * b.y, a.x * b.y + a.y * b.x);
}
__device__ __forceinline__ float2 cmulc(float2 a, float2 b) {  // conj(a)*b
    return make_float2(a.x * b.x + a.y * b.y, a.x * b.y - a.y * b.x);
}
__device__ __forceinline__ void cmadd(float2& acc, float2 a, float2 b) {
    acc.x += a.x * b.x - a.y * b.y;
    acc.y += a.x * b.y + a.y * b.x;
}

__device__ __forceinline__ float eval_poly(float x0, float x1, const float4* C) {
    float c1, s1, d1, t1;
    __sincosf(x0, &s1, &c1);
    __sincosf(x1, &t1, &d1);
    float c2 = 2.0f * c1 * c1 - 1.0f, s2 = 2.0f * s1 * c1;
    float c3 = c2 * c1 - s2 * s1,     s3 = s2 * c1 + c2 * s1;
    float d2 = 2.0f * d1 * d1 - 1.0f, t2 = 2.0f * t1 * d1;
    float d3 = d2 * d1 - t2 * t1,     t3 = t2 * d1 + d2 * t1;

    float4 A = C[0], B = C[1];
    float E = A.x + A.y * c1 + A.z * s1 + A.w * c2
            + B.x * s2 + B.y * c3 + B.z * s3;

#pragma unroll
    for (int n = 1; n <= 3; n++) {
        float4 Pa = C[2 + (n - 1) * 4];
        float4 Pb = C[3 + (n - 1) * 4];
        float4 Qa = C[4 + (n - 1) * 4];
        float4 Qb = C[5 + (n - 1) * 4];
        float P = Pa.x + Pa.y * c1 + Pa.z * s1 + Pa.w * c2
                + Pb.x * s2 + Pb.y * c3 + Pb.z * s3;
        float Q = Qa.x + Qa.y * c1 + Qa.z * s1 + Qa.w * c2
                + Qb.x * s2 + Qb.y * c3 + Qb.z * s3;
        float dn = (n == 1) ? d1 : (n == 2) ? d2 : d3;
        float tn = (n == 1) ? t1 : (n == 2) ? t2 : t3;
        E += P * dn - Q * tn;
    }
    return E;
}

// ---------------------------------------------------------------------------
// Fused kernel: 512 blocks (16 per batch) x 256 threads, 4 elems/thread.
// Prelude computes this batch's 56 packed real Fourier coefficients in shared.
// ---------------------------------------------------------------------------
__global__ __launch_bounds__(256) void qlayer(const float4* __restrict__ x,
                                              const float* __restrict__ qs,
                                              float2* __restrict__ out) {
    __shared__ float2 sg[64];      // 16 U3 gates
    __shared__ float2 sM[4][16];   // 4 block unitaries
    __shared__ float2 sS[4][16];   // amplitude spectra S[f][m0*4+m1]
    __shared__ float2 sPart[100];  // autocorr partials [coef*4 + f]
    __shared__ float2 cC[25];      // complex coefs (pre-doubled for t>0)
    __shared__ float4 sC[14];      // packed real coefs

    int b = blockIdx.x >> 4;   // 16 blocks per batch
    int t = threadIdx.x;

    // Stage A: sixteen 2x2 U3 gates
    if (t < 16) {
        const float* p = qs + ((b * 16 + t) * 3);  // (32,4,2,2,3)
        float th = p[0], ph = p[1], lam = p[2];
        float ct, st, cl, sl, cp, sp;
        __sincosf(0.5f * th, &st, &ct);
        __sincosf(lam, &sl, &cl);
        __sincosf(ph, &sp, &cp);
        float2* gd = sg + t * 4;
        gd[0] = make_float2(ct, 0.0f);
        gd[1] = make_float2(-cl * st, -sl * st);
        gd[2] = make_float2(cp * st, sp * st);
        gd[3] = make_float2((cp * cl - sp * sl) * ct, (cp * sl + sp * cl) * ct);
    }
    __syncthreads();

    // Stage B: M_i = C (U10 kron U11) C (U00 kron U01)
    if (t < 64) {
        int i = t >> 4;
        int rc = t & 15;
        int r = rc >> 2, c = rc & 3;
        const int sig[4] = {0, 1, 3, 2};  // CNOT swaps amps 2<->3
        const float2* g00 = sg + (i * 4 + 0) * 4;
        const float2* g01 = sg + (i * 4 + 1) * 4;
        const float2* g10 = sg + (i * 4 + 2) * 4;
        const float2* g11 = sg + (i * 4 + 3) * 4;
        int sr = sig[r];
        int a1 = sr >> 1, b1 = sr & 1;
        int cc = c >> 1, dc = c & 1;
        float2 acc = make_float2(0.0f, 0.0f);
#pragma unroll
        for (int m = 0; m < 4; m++) {
            int cm = m >> 1, dm = m & 1;
            int sm_ = sig[m];
            int am = sm_ >> 1, bm = sm_ & 1;
            float2 k1 = cmul(g10[a1 * 2 + cm], g11[b1 * 2 + dm]);
            float2 k0 = cmul(g00[am * 2 + cc], g01[bm * 2 + dc]);
            cmadd(acc, k1, k0);
        }
        sM[i][r * 4 + c] = acc;
    }
    __syncthreads();

    // Init spectra: state = M0 column 0 at frequency (0,0)
    if (t < 64) {
        int f = t >> 4, m = t & 15;
        sS[f][m] = (m == 0) ? sM[0][f * 4] : make_float2(0.0f, 0.0f);
    }
    __syncthreads();

    // 3 spectrum steps: S <- M_step * (freq-shift S)
#pragma unroll
    for (int step = 1; step <= 3; step++) {
        float2 val = make_float2(0.0f, 0.0f);
        int g = (t & 63) >> 4, m = t & 15;
        if (t < 64) {
            int m0 = m >> 2, m1 = m & 3;
#pragma unroll
            for (int f = 0; f < 4; f++) {
                int b0 = f >> 1, b1 = f & 1;
                if (m0 >= b0 && m1 >= b1) {
                    float2 src = sS[f][(m0 - b0) * 4 + (m1 - b1)];
                    cmadd(val, sM[step][g * 4 + f], src);
                }
            }
        }
        __syncthreads();
        if (t < 64) sS[g][m] = val;
        __syncthreads();
    }

    // Stage E1: autocorr partials per (coef, amplitude f)
    if (t < 100) {
        int c = t >> 2, f = t & 3;
        int m, n;
        if (c == 0)      { m = 0; n = 0; }
        else if (c < 4)  { m = c; n = 0; }
        else             { int idx = c - 4; n = idx / 7 + 1; m = idx % 7 - 3; }
        float sgn = (f < 2) ? 1.0f : -1.0f;
        float2 acc = make_float2(0.0f, 0.0f);
#pragma unroll
        for (int a0 = 0; a0 < 4; a0++) {
#pragma unroll
            for (int a1 = 0; a1 < 4; a1++) {
                int b0 = a0 - m, b1 = a1 - n;
                if (b0 >= 0 && b0 < 4 && b1 >= 0 && b1 < 4) {
                    float2 p = cmulc(sS[f][b0 * 4 + b1], sS[f][a0 * 4 + a1]);
                    acc.x += sgn * p.x;
                    acc.y += sgn * p.y;
                }
            }
        }
        sPart[t] = acc;
    }
    __syncthreads();

    // Stage E2: reduce over f, fold the 2x factor
    if (t < 25) {
        float2 acc = sPart[t * 4];
        acc.x += sPart[t * 4 + 1].x + sPart[t * 4 + 2].x + sPart[t * 4 + 3].x;
        acc.y += sPart[t * 4 + 1].y + sPart[t * 4 + 2].y + sPart[t * 4 + 3].y;
        if (t > 0) { acc.x *= 2.0f; acc.y *= 2.0f; }
        cC[t] = acc;
    }
    __syncthreads();

    // Stage F: repack into real basis (56 floats) in shared
    if (t < 56) {
        float val = 0.0f;
        int j = t & 7;
        int grp = t >> 3;   // 0: n=0; 1/2: n=1 P/Q; 3/4: n=2; 5/6: n=3
        if (grp == 0) {
            if (j == 0) val = cC[0].x;
            else if (j < 7) {
                int m = (j + 1) >> 1;
                val = (j & 1) ? cC[m].x : -cC[m].y;
            }
        } else {
            int n = (grp + 1) >> 1;
            bool isQ = ((grp & 1) == 0);
            int cb = 4 + (n - 1) * 7 + 3;  // m=0 slot
            if (j == 0) val = isQ ? cC[cb].y : cC[cb].x;
            else if (j < 7) {
                int m = (j + 1) >> 1;
                bool isCos = (j & 1);
                float2 cp = cC[cb + m];
                float2 cm = cC[cb - m];
                if (!isQ) val = isCos ? (cp.x + cm.x) : (cm.y - cp.y);
                else      val = isCos ? (cp.y + cm.y) : (cp.x - cm.x);
            }
        }
        ((float*)sC)[t] = val;
    }
    __syncthreads();

    // ---- Main: 4 elements per thread (2 float4 loads) ----
    int base = blockIdx.x * 512;         // float4 units per block
    int i0 = base + t;
    int i1 = base + 256 + t;
    float4 xa = x[i0];
    float4 xb = x[i1];

    float2 ra, rb;
    ra.x = eval_poly(xa.x, xa.y, sC);
    ra.y = eval_poly(xa.z, xa.w, sC);
    rb.x = eval_poly(xb.x, xb.y, sC);
    rb.y = eval_poly(xb.z, xb.w, sC);

    out[i0] = ra;
    out[i1] = rb;
}

extern "C" void kernel_launch(void* const* d_in, const int* in_sizes, int n_in,
                              void* d_out, int out_size) {
    const float* x  = (const float*)d_in[0];   // (32, 16384, 2) f32
    const float* qs = (const float*)d_in[1];   // (32, 4, 2, 2, 3) f32

    qlayer<<<512, 256>>>((const float4*)x, qs, (float2*)d_out);
}

// round 7
// speedup vs baseline: 1.0586x; 1.0586x over previous
#include <cuda_runtime.h>
#include <math.h>

#define N_B      32

// Packed real coefficients, 14 float4 per batch (see repack stage).
__device__ float4 g_coefR[N_B * 14];

__device__ __forceinline__ float2 cmul(float2 a, float2 b) {
    return make_float2(a.x * b.x - a.y * b.y, a.x * b.y + a.y * b.x);
}
__device__ __forceinline__ float2 cmulc(float2 a, float2 b) {  // conj(a)*b
    return make_float2(a.x * b.x + a.y * b.y, a.x * b.y - a.y * b.x);
}
__device__ __forceinline__ void cmadd(float2& acc, float2 a, float2 b) {
    acc.x += a.x * b.x - a.y * b.y;
    acc.y += a.x * b.y + a.y * b.x;
}

// ---------------------------------------------------------------------------
// Kernel 1: per-batch Fourier coefficients. 32 blocks x 64 threads.
// ---------------------------------------------------------------------------
__global__ __launch_bounds__(64) void coef_kernel(const float* __restrict__ qs) {
    __shared__ float2 sg[64];     // 16 U3 gates
    __shared__ float2 sM[4][16];  // 4 block unitaries
    __shared__ float2 sS[4][16];  // amplitude spectra S[f][m0*4+m1]
    __shared__ float2 cC[25];     // complex coefs (pre-doubled for t>0)

    int b = blockIdx.x;
    int t = threadIdx.x;

    // Stage A: sixteen 2x2 U3 gates
    if (t < 16) {
        const float* p = qs + ((b * 16 + t) * 3);  // (32,4,2,2,3)
        float th = p[0], ph = p[1], lam = p[2];
        float ct, st, cl, sl, cp, sp;
        __sincosf(0.5f * th, &st, &ct);
        __sincosf(lam, &sl, &cl);
        __sincosf(ph, &sp, &cp);
        float2* gd = sg + t * 4;
        gd[0] = make_float2(ct, 0.0f);
        gd[1] = make_float2(-cl * st, -sl * st);
        gd[2] = make_float2(cp * st, sp * st);
        gd[3] = make_float2((cp * cl - sp * sl) * ct, (cp * sl + sp * cl) * ct);
    }
    __syncthreads();

    // Stage B: M_i = C (U10 kron U11) C (U00 kron U01)
    {
        int i = t >> 4;
        int rc = t & 15;
        int r = rc >> 2, c = rc & 3;
        const int sig[4] = {0, 1, 3, 2};  // CNOT swaps amps 2<->3
        const float2* g00 = sg + (i * 4 + 0) * 4;
        const float2* g01 = sg + (i * 4 + 1) * 4;
        const float2* g10 = sg + (i * 4 + 2) * 4;
        const float2* g11 = sg + (i * 4 + 3) * 4;
        int sr = sig[r];
        int a1 = sr >> 1, b1 = sr & 1;
        int cc = c >> 1, dc = c & 1;
        float2 acc = make_float2(0.0f, 0.0f);
#pragma unroll
        for (int m = 0; m < 4; m++) {
            int cm = m >> 1, dm = m & 1;
            int sm_ = sig[m];
            int am = sm_ >> 1, bm = sm_ & 1;
            float2 k1 = cmul(g10[a1 * 2 + cm], g11[b1 * 2 + dm]);
            float2 k0 = cmul(g00[am * 2 + cc], g01[bm * 2 + dc]);
            cmadd(acc, k1, k0);
        }
        sM[i][r * 4 + c] = acc;
    }
    __syncthreads();

    // Init spectra
    {
        int f = t >> 4, m = t & 15;
        sS[f][m] = (m == 0) ? sM[0][f * 4] : make_float2(0.0f, 0.0f);
    }
    __syncthreads();

    // 3 spectrum steps: S <- M_step * (freq-shift S)
    for (int step = 1; step <= 3; step++) {
        int g = t >> 4, m = t & 15;
        int m0 = m >> 2, m1 = m & 3;
        float2 val = make_float2(0.0f, 0.0f);
#pragma unroll
        for (int f = 0; f < 4; f++) {
            int b0 = f >> 1, b1 = f & 1;
            if (m0 >= b0 && m1 >= b1) {
                float2 src = sS[f][(m0 - b0) * 4 + (m1 - b1)];
                cmadd(val, sM[step][g * 4 + f], src);
            }
        }
        __syncthreads();
        sS[g][m] = val;
        __syncthreads();
    }

    // Stage E: complex coefficients (autocorrelation with parity signs)
    if (t < 25) {
        int m, n;
        if (t == 0)      { m = 0; n = 0; }
        else if (t < 4)  { m = t; n = 0; }
        else             { int idx = t - 4; n = idx / 7 + 1; m = idx % 7 - 3; }
        float2 acc = make_float2(0.0f, 0.0f);
#pragma unroll
        for (int f = 0; f < 4; f++) {
            float sgn = (f < 2) ? 1.0f : -1.0f;
            for (int a0 = 0; a0 < 4; a0++) {
                for (int a1 = 0; a1 < 4; a1++) {
                    int b0 = a0 - m, b1 = a1 - n;
                    if (b0 >= 0 && b0 < 4 && b1 >= 0 && b1 < 4) {
                        float2 p = cmulc(sS[f][b0 * 4 + b1], sS[f][a0 * 4 + a1]);
                        acc.x += sgn * p.x;
                        acc.y += sgn * p.y;
                    }
                }
            }
        }
        if (t > 0) { acc.x *= 2.0f; acc.y *= 2.0f; }
        cC[t] = acc;
    }
    __syncthreads();

    // Stage F: repack into real basis, 56 floats
    if (t < 56) {
        float val = 0.0f;
        int j = t & 7;
        int grp = t >> 3;
        if (grp == 0) {
            if (j == 0) val = cC[0].x;
            else if (j < 7) {
                int m = (j + 1) >> 1;
                val = (j & 1) ? cC[m].x : -cC[m].y;
            }
        } else {
            int n = (grp + 1) >> 1;
            bool isQ = ((grp & 1) == 0);
            int cb = 4 + (n - 1) * 7 + 3;
            if (j == 0) val = isQ ? cC[cb].y : cC[cb].x;
            else if (j < 7) {
                int m = (j + 1) >> 1;
                bool isCos = (j & 1);
                float2 cp = cC[cb + m];
                float2 cm = cC[cb - m];
                if (!isQ) val = isCos ? (cp.x + cm.x) : (cm.y - cp.y);
                else      val = isCos ? (cp.y + cm.y) : (cp.x - cm.x);
            }
        }
        ((float*)g_coefR)[b * 56 + t] = val;
    }
    __syncthreads();
    // Allow the dependent eval kernel to begin; its grid-dependency sync
    // makes our g_coefR writes visible.
    cudaTriggerProgrammaticLaunchCompletion();
}

// ---------------------------------------------------------------------------
// Kernel 2: real trig-poly evaluation. 512 blocks x 256 thr, 4 elems/thread.
// ---------------------------------------------------------------------------
__device__ __forceinline__ float eval_poly(float x0, float x1, const float4* C) {
    float c1, s1, d1, t1;
    __sincosf(x0, &s1, &c1);
    __sincosf(x1, &t1, &d1);
    float c2 = 2.0f * c1 * c1 - 1.0f, s2 = 2.0f * s1 * c1;
    float c3 = c2 * c1 - s2 * s1,     s3 = s2 * c1 + c2 * s1;
    float d2 = 2.0f * d1 * d1 - 1.0f, t2 = 2.0f * t1 * d1;
    float d3 = d2 * d1 - t2 * t1,     t3 = t2 * d1 + d2 * t1;

    float4 A = C[0], B = C[1];
    float E = A.x + A.y * c1 + A.z * s1 + A.w * c2
            + B.x * s2 + B.y * c3 + B.z * s3;

#pragma unroll
    for (int n = 1; n <= 3; n++) {
        float4 Pa = C[2 + (n - 1) * 4];
        float4 Pb = C[3 + (n - 1) * 4];
        float4 Qa = C[4 + (n - 1) * 4];
        float4 Qb = C[5 + (n - 1) * 4];
        float P = Pa.x + Pa.y * c1 + Pa.z * s1 + Pa.w * c2
                + Pb.x * s2 + Pb.y * c3 + Pb.z * s3;
        float Q = Qa.x + Qa.y * c1 + Qa.z * s1 + Qa.w * c2
                + Qb.x * s2 + Qb.y * c3 + Qb.z * s3;
        float dn = (n == 1) ? d1 : (n == 2) ? d2 : d3;
        float tn = (n == 1) ? t1 : (n == 2) ? t2 : t3;
        E += P * dn - Q * tn;
    }
    return E;
}

__global__ __launch_bounds__(256) void eval_kernel(const float4* __restrict__ x,
                                                   float2* __restrict__ out) {
    __shared__ float4 sC[14];
    int b = blockIdx.x >> 4;          // 16 blocks per batch
    int t = threadIdx.x;

    // Issue x loads FIRST (independent of the coef kernel)
    int base = blockIdx.x * 512;      // float4 units per block
    int i0 = base + t;
    int i1 = base + 256 + t;
    float4 xa = x[i0];
    float4 xb = x[i1];

    // Now wait for the coef kernel's results
    cudaGridDependencySynchronize();
    if (t < 14) sC[t] = g_coefR[b * 14 + t];
    __syncthreads();

    float2 ra, rb;
    ra.x = eval_poly(xa.x, xa.y, sC);
    ra.y = eval_poly(xa.z, xa.w, sC);
    rb.x = eval_poly(xb.x, xb.y, sC);
    rb.y = eval_poly(xb.z, xb.w, sC);

    out[i0] = ra;
    out[i1] = rb;
}

extern "C" void kernel_launch(void* const* d_in, const int* in_sizes, int n_in,
                              void* d_out, int out_size) {
    const float* x  = (const float*)d_in[0];   // (32, 16384, 2) f32
    const float* qs = (const float*)d_in[1];   // (32, 4, 2, 2, 3) f32

    coef_kernel<<<N_B, 64>>>(qs);

    cudaLaunchConfig_t cfg = {};
    cfg.gridDim = dim3(512, 1, 1);
    cfg.blockDim = dim3(256, 1, 1);
    cfg.dynamicSmemBytes = 0;
    cfg.stream = 0;
    cudaLaunchAttribute attr[1];
    attr[0].id = cudaLaunchAttributeProgrammaticStreamSerialization;
    attr[0].val.programmaticStreamSerializationAllowed = 1;
    cfg.attrs = attr;
    cfg.numAttrs = 1;
    cudaLaunchKernelEx(&cfg, eval_kernel, (const float4*)x, (float2*)d_out);
}